// round 1
// baseline (speedup 1.0000x reference)
#include <cuda_runtime.h>
#include <cstdint>

// Problem constants (fixed shapes per reference)
static constexpr int Bn    = 512;     // batch
static constexpr int Ln    = 8192;    // doc length
static constexpr int Nn    = 128;     // output_sentence_num
static constexpr int Sn    = 256;     // output_sentence_len
static constexpr int DELIM = 5;
static constexpr int TPB   = 512;     // threads per block
static constexpr int TOKS  = Ln / TPB; // 16 tokens per thread

// FULL = true  : d_out is float32 [ otp(B*N*S) | len_doc(B) | mask(B*N*S) ]
// FULL = false : d_out is int32 otp only (B*N*S)
template <bool FULL>
__global__ __launch_bounds__(TPB, 2)
void split_kernel(const int* __restrict__ x, void* __restrict__ out_raw)
{
    __shared__ int s_dpos[Nn - 1];   // positions of first 127 delimiters
    __shared__ int s_woff[16];       // per-warp scan offsets
    __shared__ int s_D;              // total delimiter count in row
    __shared__ int s_doc;            // # nonempty sentences

    const int b    = blockIdx.x;
    const int t    = threadIdx.x;
    const int lane = t & 31;
    const int warp = t >> 5;

    if (t == 0) s_doc = 0;

    const int* __restrict__ xrow = x + (size_t)b * Ln;

    // ---------------- Pass 1: count delimiters per thread (16 contiguous tokens) ----
    const int base = t * TOKS;
    const int4* x4 = reinterpret_cast<const int4*>(xrow + base);
    int4 v0 = x4[0], v1 = x4[1], v2 = x4[2], v3 = x4[3];

    int cnt = 0;
    cnt += (v0.x == DELIM) + (v0.y == DELIM) + (v0.z == DELIM) + (v0.w == DELIM);
    cnt += (v1.x == DELIM) + (v1.y == DELIM) + (v1.z == DELIM) + (v1.w == DELIM);
    cnt += (v2.x == DELIM) + (v2.y == DELIM) + (v2.z == DELIM) + (v2.w == DELIM);
    cnt += (v3.x == DELIM) + (v3.y == DELIM) + (v3.z == DELIM) + (v3.w == DELIM);

    // warp inclusive scan
    int incl = cnt;
    #pragma unroll
    for (int o = 1; o < 32; o <<= 1) {
        int n = __shfl_up_sync(0xffffffffu, incl, o);
        if (lane >= o) incl += n;
    }
    if (lane == 31) s_woff[warp] = incl;
    __syncthreads();

    if (warp == 0 && lane < 16) {
        int my  = s_woff[lane];
        int inc = my;
        #pragma unroll
        for (int o = 1; o < 16; o <<= 1) {
            int n = __shfl_up_sync(0x0000ffffu, inc, o);
            if (lane >= o) inc += n;
        }
        s_woff[lane] = inc - my;      // exclusive offset for this warp
        if (lane == 15) s_D = inc;    // total
    }
    __syncthreads();

    const int excl = incl - cnt + s_woff[warp];

    // ---------------- Pass 2: record first 127 delimiter positions -----------------
    if (cnt > 0 && excl < Nn - 1) {
        int r = excl;
        int p = base;
        #pragma unroll
        for (int i = 0; i < 4; i++) {
            int4 w = (i == 0) ? v0 : (i == 1) ? v1 : (i == 2) ? v2 : v3;
            if (w.x == DELIM) { if (r < Nn - 1) s_dpos[r] = p + 0; r++; }
            if (w.y == DELIM) { if (r < Nn - 1) s_dpos[r] = p + 1; r++; }
            if (w.z == DELIM) { if (r < Nn - 1) s_dpos[r] = p + 2; r++; }
            if (w.w == DELIM) { if (r < Nn - 1) s_dpos[r] = p + 3; r++; }
            p += 4;
        }
    }
    __syncthreads();

    const int D = s_D;

    float* otp_f  = nullptr; float* len_f = nullptr; float* mask_f = nullptr;
    int*   otp_i  = nullptr;
    if (FULL) {
        otp_f  = reinterpret_cast<float*>(out_raw);
        len_f  = otp_f + (size_t)Bn * Nn * Sn;
        mask_f = len_f + Bn;
    } else {
        otp_i  = reinterpret_cast<int*>(out_raw);
    }

    // ---------------- Emit: one warp per segment ----------------
    int doc_local = 0;
    for (int k = warp; k < Nn; k += 16) {
        int start = 0, size = 0;
        if (k <= D) {
            start = (k == 0) ? 0 : (s_dpos[k - 1] + 1);
            if (k == Nn - 1 || k == D) size = (Ln + 1) - start;   // tail-merged / last
            else                        size = s_dpos[k] + 1 - start;
        }
        const bool writeseg = (size > 1); // lone-delimiter chunks -> all PAD

        const size_t row_off = ((size_t)b * Nn + k) * Sn;
        int nz = 0;
        #pragma unroll
        for (int i = 0; i < Sn / 32; i++) {
            const int s = lane + i * 32;
            int val = 0;
            if (writeseg && s < size) {
                const int j = start + s;
                val = (j < Ln) ? xrow[j] : DELIM;   // rpad: trailing delimiter
            }
            if (FULL) otp_f[row_off + s] = (float)val;
            else      otp_i[row_off + s] = val;
            nz += (val != 0);
        }
        // warp reduce nonzero count -> len_sent
        #pragma unroll
        for (int o = 16; o > 0; o >>= 1) nz += __shfl_down_sync(0xffffffffu, nz, o);
        nz = __shfl_sync(0xffffffffu, nz, 0);
        if (lane == 0 && nz > 0) doc_local++;

        if (FULL) {
            #pragma unroll
            for (int i = 0; i < Sn / 32; i++) {
                const int s = lane + i * 32;
                mask_f[row_off + s] = (s < nz) ? 1.0f : 0.0f;
            }
        }
    }

    if (FULL) {
        if (lane == 0 && doc_local > 0) atomicAdd(&s_doc, doc_local);
        __syncthreads();
        if (t == 0) len_f[b] = (float)s_doc;
    }
}

extern "C" void kernel_launch(void* const* d_in, const int* in_sizes, int n_in,
                              void* d_out, int out_size)
{
    const int* x = (const int*)d_in[0];
    const long long full = 2LL * Bn * Nn * Sn + Bn;

    if ((long long)out_size >= full) {
        split_kernel<true><<<Bn, TPB>>>(x, d_out);
    } else {
        split_kernel<false><<<Bn, TPB>>>(x, d_out);
    }
}